// round 17
// baseline (speedup 1.0000x reference)
#include <cuda_runtime.h>
#include <cuda_bf16.h>
#include <cstdint>

#define NN   50000
#define NE   800000
#define DIN  128
#define DH   256
#define NG   256
#define DH2  128
#define NSM  148

// ---------------- scratch (device globals; no allocations allowed) ----------
__device__ __nv_bfloat16 g_hb [(size_t)NN * DIN];  // input h, bf16
__device__ __nv_bfloat16 g_h1 [(size_t)NN * DH];   // layer-1 output, bf16
__device__ __nv_bfloat16 g_h2 [(size_t)NN * DH];   // layer-2 output, bf16
__device__ __nv_bfloat16 g_w1 [DH * DIN];          // W1^T bf16
__device__ __nv_bfloat16 g_w2 [DH * DH];           // W2^T bf16
__device__ int g_deg[NN];
__device__ int g_rowptr[NN + 1];
__device__ int g_pos[NN];
__device__ int g_esrc[NE];

// ---------------- helpers ---------------------------------------------------
__device__ __forceinline__ uint32_t smem_u32(const void* p) {
    uint32_t a;
    asm("{ .reg .u64 t; cvta.to.shared.u64 t, %1; cvt.u32.u64 %0, t; }"
        : "=r"(a) : "l"(p));
    return a;
}

__device__ __forceinline__ void ldm_x4(uint32_t* f, uint32_t sa) {
    asm volatile("ldmatrix.sync.aligned.m8n8.x4.shared.b16 {%0,%1,%2,%3}, [%4];"
                 : "=r"(f[0]), "=r"(f[1]), "=r"(f[2]), "=r"(f[3]) : "r"(sa));
}

__device__ __forceinline__ void mma16816(float* c, const uint32_t* a, const uint32_t* b) {
    asm volatile(
        "mma.sync.aligned.m16n8k16.row.col.f32.bf16.bf16.f32 "
        "{%0,%1,%2,%3}, {%4,%5,%6,%7}, {%8,%9}, {%0,%1,%2,%3};"
        : "+f"(c[0]), "+f"(c[1]), "+f"(c[2]), "+f"(c[3])
        : "r"(a[0]), "r"(a[1]), "r"(a[2]), "r"(a[3]), "r"(b[0]), "r"(b[1]));
}

__device__ __forceinline__ void acc_u2(float* acc, uint2 u) {
    float2 a = __bfloat1622float2(*(__nv_bfloat162*)&u.x);
    float2 b = __bfloat1622float2(*(__nv_bfloat162*)&u.y);
    acc[0] += a.x; acc[1] += a.y; acc[2] += b.x; acc[3] += b.y;
}
__device__ __forceinline__ void acc_u4(float* acc, uint4 u) {
    float2 a = __bfloat1622float2(*(__nv_bfloat162*)&u.x);
    float2 b = __bfloat1622float2(*(__nv_bfloat162*)&u.y);
    float2 c = __bfloat1622float2(*(__nv_bfloat162*)&u.z);
    float2 d = __bfloat1622float2(*(__nv_bfloat162*)&u.w);
    acc[0] += a.x; acc[1] += a.y; acc[2] += b.x; acc[3] += b.y;
    acc[4] += c.x; acc[5] += c.y; acc[6] += d.x; acc[7] += d.y;
}

__device__ __forceinline__ void conv_h_item(const float* __restrict__ h, int i) {
    float4 v = __ldg((const float4*)h + i);
    __nv_bfloat16 b[4] = { __float2bfloat16(v.x), __float2bfloat16(v.y),
                           __float2bfloat16(v.z), __float2bfloat16(v.w) };
    *(uint2*)(g_hb + 4 * (size_t)i) = *(uint2*)b;
}

// ---- work split constants ---------------------------------------------------
#define PREP_H_ITEMS   (NN * DIN / 4)            // 1,600,000 float4 items
#define H1_ITEMS       614400                    // done inside k_scan_conv
#define H2_ITEMS       (PREP_H_ITEMS - H1_ITEMS) // done inside k_scatter_conv
#define PREP_W1_ITEMS  (DH * DIN)                // 32,768
#define PREP_W2_ITEMS  (DH * DH)                 // 65,536
#define HISTW_TOTAL    (NE + PREP_W1_ITEMS + PREP_W2_ITEMS)

// ---------------- zero degree ------------------------------------------------
__global__ void k_zero() {
    int i = blockIdx.x * blockDim.x + threadIdx.x;
    if (i < NN) g_deg[i] = 0;
}

// -------- edge histogram + W transposes (W rides in hist's idle capacity) ---
__global__ void k_hist_w(const int* __restrict__ dst,
                         const float* __restrict__ W1,
                         const float* __restrict__ W2) {
    int i = blockIdx.x * blockDim.x + threadIdx.x;
    if (i < NE) { atomicAdd(&g_deg[dst[i]], 1); return; }
    i -= NE;
    if (i < PREP_W1_ITEMS) {
        int n = i / DIN, k = i % DIN;
        g_w1[i] = __float2bfloat16(W1[(size_t)k * DH + n]);
        return;
    }
    i -= PREP_W1_ITEMS;
    if (i < PREP_W2_ITEMS) {
        int n = i / DH, k = i % DH;
        g_w2[i] = __float2bfloat16(W2[(size_t)k * DH + n]);
    }
}

// -------- scan (block 0) + h->bf16 conversion part 1 (blocks 1..) -----------
#define SCAN_CONV_BLKS (1 + (H1_ITEMS + 1023) / 1024)   // 601

__global__ void k_scan_conv(const float* __restrict__ h) {
    if (blockIdx.x > 0) {
        int idx = (blockIdx.x - 1) * 1024 + threadIdx.x;
        if (idx < H1_ITEMS) conv_h_item(h, idx);
        return;
    }
    const int CH = 49;
    int t = threadIdx.x;
    int beg = t * CH;
    int end = beg + CH; if (end > NN) end = NN;
    int s = 0;
    for (int i = beg; i < end; ++i) s += g_deg[i];
    int lane = t & 31, w = t >> 5;
    int v = s;
#pragma unroll
    for (int o = 1; o < 32; o <<= 1) {
        int u = __shfl_up_sync(0xffffffffu, v, o);
        if (lane >= o) v += u;
    }
    __shared__ int wsum[32];
    if (lane == 31) wsum[w] = v;
    __syncthreads();
    if (w == 0) {
        int x = wsum[lane];
#pragma unroll
        for (int o = 1; o < 32; o <<= 1) {
            int u = __shfl_up_sync(0xffffffffu, x, o);
            if (lane >= o) x += u;
        }
        wsum[lane] = x;
    }
    __syncthreads();
    int excl = v - s + (w > 0 ? wsum[w - 1] : 0);
    for (int i = beg; i < end; ++i) {
        int d = g_deg[i];
        g_rowptr[i] = excl;
        g_pos[i]    = excl;
        excl += d;
    }
    if (t == 1023) g_rowptr[NN] = wsum[31];
}

// -------- scatter + h->bf16 conversion part 2 --------------------------------
#define SCAT_BLKS      ((NE + 1023) / 1024)             // 782
#define SCAT_CONV_BLKS (SCAT_BLKS + (H2_ITEMS + 1023) / 1024)

__global__ void k_scatter_conv(const int* __restrict__ src, const int* __restrict__ dst,
                               const float* __restrict__ h) {
    if (blockIdx.x < SCAT_BLKS) {
        int e = blockIdx.x * 1024 + threadIdx.x;
        if (e < NE) {
            int p = atomicAdd(&g_pos[dst[e]], 1);
            g_esrc[p] = src[e];
        }
        return;
    }
    int idx = (blockIdx.x - SCAT_BLKS) * 1024 + threadIdx.x + H1_ITEMS;
    if (idx < PREP_H_ITEMS) conv_h_item(h, idx);
}

// ===== FUSED persistent warp-specialized agg + HMMA GEMM =====================
// C = relu(mean_agg(Hin) @ Bw^T + bias); Hin [NN x K] bf16; Bw [256 x K] bf16.
// 148 CTAs, 512 threads: warps 0-7 consumers (MMA), warps 8-15 producers
// (gather+mean -> A ping-pong smem). B fully smem-resident. BM=64, BN=256.
#define BM_F 64

template <int K>
__global__ __launch_bounds__(512, 1) void k_fused(
    const __nv_bfloat16* __restrict__ Hin,
    const __nv_bfloat16* __restrict__ Bw,
    const float* __restrict__ bias,
    __nv_bfloat16* __restrict__ C)
{
    constexpr int LDK     = K + 8;                 // padded row (bf16)
    constexpr int B_BYTES = 256 * LDK * 2;
    constexpr int A_BYTES = BM_F * LDK * 2;
    constexpr int NT      = (NN + BM_F - 1) / BM_F;

    extern __shared__ char dsm[];
    char* smB = dsm;
    char* smA0 = dsm + B_BYTES;
    const uint32_t sB  = smem_u32(smB);
    const uint32_t sA0 = sB + B_BYTES;

    const int tid  = threadIdx.x;
    const int lane = tid & 31;
    const int wid  = tid >> 5;
    const int bid  = blockIdx.x;

    // ---- preload full B (all warps) ----------------------------------------
    for (int i = tid; i < 256 * K / 8; i += 512) {
        int r = i / (K / 8), c8 = i % (K / 8);
        *(uint4*)(smB + (r * LDK + c8 * 8) * 2) =
            *(const uint4*)(Bw + (size_t)r * K + c8 * 8);
    }

    // number of tiles this CTA owns: tiles bid, bid+148, ...
    const int nt_mine = (bid < NT) ? ((NT - 1 - bid) / NSM + 1) : 0;

    if (wid >= 8) {
        // =================== PRODUCER warps (8) =============================
        const int pw = wid - 8;
        constexpr int V = K / 32;          // bf16 per lane: 4 or 8
        const size_t lo = (size_t)lane * V;
        for (int it = 0; it <= nt_mine; ++it) {
            __syncthreads();
            if (it >= nt_mine) continue;
            int t = bid + it * NSM;
            char* smA = smA0 + (it & 1) * A_BYTES;
            int m0 = t * BM_F;
#pragma unroll 1
            for (int j = 0; j < 8; ++j) {
                int nd = pw * 8 + j;
                int row = m0 + nd;
                if (row >= NN) break;
                int beg = g_rowptr[row];
                int end = g_rowptr[row + 1];
                float acc[V];
#pragma unroll
                for (int q = 0; q < V; ++q) acc[q] = 0.f;
                int e = beg;
                for (; e + 3 < end; e += 4) {
                    int s0 = g_esrc[e], s1 = g_esrc[e + 1];
                    int s2 = g_esrc[e + 2], s3 = g_esrc[e + 3];
                    if constexpr (V == 4) {
                        uint2 u0 = __ldg((const uint2*)(Hin + (size_t)s0 * K + lo));
                        uint2 u1 = __ldg((const uint2*)(Hin + (size_t)s1 * K + lo));
                        uint2 u2 = __ldg((const uint2*)(Hin + (size_t)s2 * K + lo));
                        uint2 u3 = __ldg((const uint2*)(Hin + (size_t)s3 * K + lo));
                        acc_u2(acc, u0); acc_u2(acc, u1); acc_u2(acc, u2); acc_u2(acc, u3);
                    } else {
                        uint4 u0 = __ldg((const uint4*)(Hin + (size_t)s0 * K + lo));
                        uint4 u1 = __ldg((const uint4*)(Hin + (size_t)s1 * K + lo));
                        uint4 u2 = __ldg((const uint4*)(Hin + (size_t)s2 * K + lo));
                        uint4 u3 = __ldg((const uint4*)(Hin + (size_t)s3 * K + lo));
                        acc_u4(acc, u0); acc_u4(acc, u1); acc_u4(acc, u2); acc_u4(acc, u3);
                    }
                }
                for (; e < end; ++e) {
                    int s0 = g_esrc[e];
                    if constexpr (V == 4) {
                        uint2 u0 = __ldg((const uint2*)(Hin + (size_t)s0 * K + lo));
                        acc_u2(acc, u0);
                    } else {
                        uint4 u0 = __ldg((const uint4*)(Hin + (size_t)s0 * K + lo));
                        acc_u4(acc, u0);
                    }
                }
                float inv = (end > beg) ? (1.f / (float)(end - beg)) : 0.f;
                __nv_bfloat16 o[V];
#pragma unroll
                for (int q = 0; q < V; ++q) o[q] = __float2bfloat16(acc[q] * inv);
                char* dstp = smA + (nd * LDK + lane * V) * 2;
                if constexpr (V == 4) *(uint2*)dstp = *(uint2*)o;
                else                  *(uint4*)dstp = *(uint4*)o;
            }
        }
    } else {
        // =================== CONSUMER warps (8) =============================
        const int wm = (wid & 1) * 32;         // M offset (tile is 64 rows)
        const int wn = (wid >> 1) * 64;        // N offset (256 cols)

        const int aq = lane >> 3, ar = lane & 7;
        const int a_row = ar + (aq & 1) * 8;
        const int a_col = (aq >> 1) * 8;
        uint32_t aoff[2];
#pragma unroll
        for (int i = 0; i < 2; ++i)
            aoff[i] = (uint32_t)(((wm + i * 16 + a_row) * LDK + a_col) * 2);
        const int b_row = (aq >> 1) * 8 + ar;
        const int b_col = (aq & 1) * 8;
        uint32_t boff[4];
#pragma unroll
        for (int jp = 0; jp < 4; ++jp)
            boff[jp] = (uint32_t)(((wn + jp * 16 + b_row) * LDK + b_col) * 2);

        const int g   = lane >> 2;
        const int tig = lane & 3;

        for (int it = 0; it <= nt_mine; ++it) {
            __syncthreads();
            if (it < 1) continue;
            int t = bid + (it - 1) * NSM;
            uint32_t sA = sA0 + (uint32_t)((it - 1) & 1) * A_BYTES;
            int m0 = t * BM_F;

            float c[2][8][4];
#pragma unroll
            for (int i = 0; i < 2; ++i)
#pragma unroll
                for (int j = 0; j < 8; ++j)
#pragma unroll
                    for (int q = 0; q < 4; ++q) c[i][j][q] = 0.f;

            const int NKS = K / 16;
#pragma unroll
            for (int ks = 0; ks < NKS; ++ks) {
                uint32_t kb = (uint32_t)(ks * 32);   // 16 bf16 cols = 32 bytes
                uint32_t af[2][4];
#pragma unroll
                for (int i = 0; i < 2; ++i) ldm_x4(af[i], sA + aoff[i] + kb);
#pragma unroll
                for (int jp = 0; jp < 4; ++jp) {
                    uint32_t bf[4];
                    ldm_x4(bf, sB + boff[jp] + kb);
#pragma unroll
                    for (int i = 0; i < 2; ++i) {
#pragma unroll
                        for (int jj = 0; jj < 2; ++jj)
                            mma16816(c[i][jp * 2 + jj], af[i], bf + jj * 2);
                    }
                }
            }

            // epilogue: bias + relu, bf16 store
#pragma unroll
            for (int i = 0; i < 2; ++i) {
#pragma unroll
                for (int j = 0; j < 8; ++j) {
                    int col  = wn + j * 8 + 2 * tig;
                    float b0 = bias[col], b1 = bias[col + 1];
                    int r0 = m0 + wm + i * 16 + g;
                    if (r0 < NN) {
                        __nv_bfloat162 o = __floats2bfloat162_rn(
                            fmaxf(c[i][j][0] + b0, 0.f), fmaxf(c[i][j][1] + b1, 0.f));
                        *(__nv_bfloat162*)(C + (size_t)r0 * 256 + col) = o;
                    }
                    int r1 = r0 + 8;
                    if (r1 < NN) {
                        __nv_bfloat162 o = __floats2bfloat162_rn(
                            fmaxf(c[i][j][2] + b0, 0.f), fmaxf(c[i][j][3] + b1, 0.f));
                        *(__nv_bfloat162*)(C + (size_t)r1 * 256 + col) = o;
                    }
                }
            }
        }
    }
}

#define FUSED_SMEM(K) ((256 * ((K) + 8) * 2) + 2 * (BM_F * ((K) + 8) * 2))

// -------- fused per-graph readout + MLP (graph_ids sorted) ------------------
__global__ __launch_bounds__(256) void k_readout_mlp(
    const int* __restrict__ gids,
    const float* __restrict__ Wr1, const float* __restrict__ br1,
    const float* __restrict__ Wr2, const float* __restrict__ br2,
    float* __restrict__ out)
{
    int g = blockIdx.x;
    int f = threadIdx.x;                 // 256 threads
    __shared__ int sb_, se_;
    __shared__ float shg[DH];
    __shared__ float ws[4];
    if (f == 0) {
        int lo = 0, hi = NN;
        while (lo < hi) { int mid = (lo + hi) >> 1; if (gids[mid] < g) lo = mid + 1; else hi = mid; }
        sb_ = lo;
        lo = 0; hi = NN;
        while (lo < hi) { int mid = (lo + hi) >> 1; if (gids[mid] < g + 1) lo = mid + 1; else hi = mid; }
        se_ = lo;
    }
    __syncthreads();
    int beg = sb_, end = se_;
    float acc = 0.f;
    int n = beg;
    for (; n + 3 < end; n += 4) {
        float v0 = __bfloat162float(__ldg(g_h2 + (size_t)(n + 0) * DH + f));
        float v1 = __bfloat162float(__ldg(g_h2 + (size_t)(n + 1) * DH + f));
        float v2 = __bfloat162float(__ldg(g_h2 + (size_t)(n + 2) * DH + f));
        float v3 = __bfloat162float(__ldg(g_h2 + (size_t)(n + 3) * DH + f));
        acc += (v0 + v1) + (v2 + v3);
    }
    for (; n < end; ++n)
        acc += __bfloat162float(__ldg(g_h2 + (size_t)n * DH + f));
    shg[f] = acc / fmaxf((float)(end - beg), 1.f);
    __syncthreads();

    if (f < DH2) {
        float hac = br1[f];
#pragma unroll 4
        for (int k = 0; k < DH; ++k) hac += shg[k] * Wr1[k * DH2 + f];
        float v = hac * Wr2[f];
#pragma unroll
        for (int off = 16; off > 0; off >>= 1) v += __shfl_down_sync(0xffffffffu, v, off);
        if ((f & 31) == 0) ws[f >> 5] = v;
    }
    __syncthreads();
    if (f == 0) out[g] = ws[0] + ws[1] + ws[2] + ws[3] + br2[0];
}

// ---------------- launch ----------------------------------------------------
extern "C" void kernel_launch(void* const* d_in, const int* in_sizes, int n_in,
                              void* d_out, int out_size) {
    const float* h    = (const float*)d_in[0];
    const int*   src  = (const int*)  d_in[1];
    const int*   dst  = (const int*)  d_in[2];
    const int*   gids = (const int*)  d_in[3];
    const float* W1   = (const float*)d_in[4];
    const float* b1   = (const float*)d_in[5];
    const float* W2   = (const float*)d_in[6];
    const float* b2   = (const float*)d_in[7];
    const float* Wr1  = (const float*)d_in[8];
    const float* br1  = (const float*)d_in[9];
    const float* Wr2  = (const float*)d_in[10];
    const float* br2  = (const float*)d_in[11];
    float* out = (float*)d_out;

    __nv_bfloat16 *hb, *h1, *h2, *w1, *w2;
    cudaGetSymbolAddress((void**)&hb, g_hb);
    cudaGetSymbolAddress((void**)&h1, g_h1);
    cudaGetSymbolAddress((void**)&h2, g_h2);
    cudaGetSymbolAddress((void**)&w1, g_w1);
    cudaGetSymbolAddress((void**)&w2, g_w2);

    cudaFuncSetAttribute(k_fused<DIN>, cudaFuncAttributeMaxDynamicSharedMemorySize, FUSED_SMEM(DIN));
    cudaFuncSetAttribute(k_fused<DH>,  cudaFuncAttributeMaxDynamicSharedMemorySize, FUSED_SMEM(DH));

    // CSR build + prep (W-prep hidden in hist, h-conv hidden in scan/scatter)
    k_zero<<<(NN + 255) / 256, 256>>>();
    k_hist_w<<<(HISTW_TOTAL + 255) / 256, 256>>>(dst, W1, W2);
    k_scan_conv<<<SCAN_CONV_BLKS, 1024>>>(h);
    k_scatter_conv<<<SCAT_CONV_BLKS, 1024>>>(src, dst, h);

    // layer 1 (fused persistent agg+gemm)
    k_fused<DIN><<<NSM, 512, FUSED_SMEM(DIN)>>>(hb, w1, b1, h1);
    // layer 2
    k_fused<DH><<<NSM, 512, FUSED_SMEM(DH)>>>(h1, w2, b2, h2);

    // fused readout + MLP
    k_readout_mlp<<<NG, 256>>>(gids, Wr1, br1, Wr2, br2, out);
}